// round 15
// baseline (speedup 1.0000x reference)
#include <cuda_runtime.h>
#include <cuda_fp16.h>
#include <stdint.h>
#include <math.h>

#define NTOT 256
#define CCH  256
#define KDIM 12544

__device__ __half g_roi [(size_t)NTOT * KDIM];      // A matrix, k = pq*256 + c
__device__ __half g_bh  [(size_t)CCH  * KDIM];      // conv_w fp16, k = pq*256 + c
__device__ __half g_imgT[(size_t)4 * 4096 * 256];   // image [b][y*64+x][c] fp16
__device__ float  g_part[(size_t)37 * 65536];       // split-K partials

// ============================================================================
// helpers
// ============================================================================
__device__ __forceinline__ uint32_t smem_u32(const void* p) {
    uint32_t a;
    asm("{ .reg .u64 t; cvta.to.shared.u64 t, %1; cvt.u32.u64 %0, t; }"
        : "=r"(a) : "l"(p));
    return a;
}
__device__ __forceinline__ void cpasync16(uint32_t dst, const void* src) {
    asm volatile("cp.async.cg.shared.global [%0], [%1], 16;" :: "r"(dst), "l"(src));
}
#define CP_COMMIT() asm volatile("cp.async.commit_group;" ::: "memory")
#define CP_WAIT(n)  asm volatile("cp.async.wait_group %0;" :: "n"(n) : "memory")

__device__ __forceinline__ void mma_f16(float c[4], const uint32_t a[4], const uint32_t b[2]) {
    asm volatile(
        "mma.sync.aligned.m16n8k16.row.col.f32.f16.f16.f32 "
        "{%0,%1,%2,%3}, {%4,%5,%6,%7}, {%8,%9}, {%0,%1,%2,%3};"
        : "+f"(c[0]), "+f"(c[1]), "+f"(c[2]), "+f"(c[3])
        : "r"(a[0]), "r"(a[1]), "r"(a[2]), "r"(a[3]), "r"(b[0]), "r"(b[1]));
}
__device__ __forceinline__ void ldsm_x4(uint32_t r[4], uint32_t addr) {
    asm volatile("ldmatrix.sync.aligned.m8n8.x4.shared.b16 {%0,%1,%2,%3}, [%4];"
        : "=r"(r[0]), "=r"(r[1]), "=r"(r[2]), "=r"(r[3]) : "r"(addr));
}

// ============================================================================
// Kernel T: transpose img [b][c][yx] fp32 -> g_imgT [b][yx][c] fp16
// ============================================================================
__global__ __launch_bounds__(256) void trans_kernel(const float* __restrict__ img) {
    __shared__ float tile[64][65];
    int yx0 = blockIdx.x * 64, c0 = blockIdx.y * 64, b = blockIdx.z;
    int tid = threadIdx.x;
    const float* src = img + ((size_t)b * 256 + c0) * 4096 + yx0;
    #pragma unroll
    for (int j = 0; j < 16; j++) {
        int idx = tid + j * 256;
        int row = idx >> 6, col = idx & 63;
        tile[row][col] = src[(size_t)row * 4096 + col];
    }
    __syncthreads();
    #pragma unroll
    for (int pass = 0; pass < 2; pass++) {
        int tt = tid + pass * 256;
        int w = tt >> 3, cc = (tt & 7) * 8;
        __half2 h0 = __floats2half2_rn(tile[cc + 0][w], tile[cc + 1][w]);
        __half2 h1 = __floats2half2_rn(tile[cc + 2][w], tile[cc + 3][w]);
        __half2 h2 = __floats2half2_rn(tile[cc + 4][w], tile[cc + 5][w]);
        __half2 h3 = __floats2half2_rn(tile[cc + 6][w], tile[cc + 7][w]);
        uint4 u;
        u.x = *(uint32_t*)&h0; u.y = *(uint32_t*)&h1;
        u.z = *(uint32_t*)&h2; u.w = *(uint32_t*)&h3;
        *(uint4*)(g_imgT + ((size_t)b * 4096 + yx0 + w) * 256 + c0 + cc) = u;
    }
}

// ============================================================================
// Kernel P: permute+convert conv_w [o][c][pq] fp32 -> g_bh [o][pq*256+c] fp16
// ============================================================================
__global__ __launch_bounds__(128) void convp_kernel(const float* __restrict__ w) {
    __shared__ float buf[128 * 49];
    int o = blockIdx.x, tid = threadIdx.x;
    #pragma unroll
    for (int h = 0; h < 2; h++) {
        const float* src = w + (size_t)o * KDIM + h * 128 * 49;
        #pragma unroll
        for (int j = 0; j < 49; j++) buf[j * 128 + tid] = src[j * 128 + tid];
        __syncthreads();
        __half* dst = g_bh + (size_t)o * KDIM + h * 128 + tid;
        #pragma unroll
        for (int j = 0; j < 49; j++)
            dst[j * 256] = __float2half_rn(buf[tid * 49 + j]);
        __syncthreads();
    }
}

// ============================================================================
// Kernel A (roi v6 + nbase): grid (128,4), block 224 = 7q x 32cp.
// ============================================================================
__global__ __launch_bounds__(224) void roi_kernel(const float* __restrict__ boxes,
                                                  int nbase) {
    __shared__ __half2 whx[7][4];
    __shared__ float   swy[7][4];
    __shared__ int     sxq[7], syq[7];
    __shared__ __half2 tmp[7][20][32];

    int n   = nbase + blockIdx.x;
    int cg  = blockIdx.y;
    int b   = n >> 6;
    int tid = threadIdx.x;
    int cp  = tid & 31;
    int q   = tid >> 5;

    if (tid < 14) {
        int qq = tid >> 1, axis = tid & 1;
        const float nsc = 64.0f / 63.0f;
        float lo = boxes[n * 4 + axis]     * nsc;
        float hi = boxes[n * 4 + 2 + axis] * nsc;
        float span = hi - lo;
        float hs = span * (1.0f / 42.0f);
        float w4[4] = {0.f, 0.f, 0.f, 0.f};
        int sx = 0;
        #pragma unroll
        for (int s = 0; s < 3; s++) {
            int i = qq * 3 + s;
            float t = (float)i * (1.0f / 20.0f);
            float gg = lo + hs + t * (span - 2.0f * hs);
            float p = gg * 63.0f;
            float f = floorf(p);
            int x0 = (int)f;
            float w = p - f;
            if (s == 0) sx = x0;
            int d = x0 - sx;
            w4[d]     += (1.0f - w) * (1.0f / 3.0f);
            w4[d + 1] += w * (1.0f / 3.0f);
        }
        if (axis == 0) {
            sxq[qq] = sx;
            #pragma unroll
            for (int i = 0; i < 4; i++) {
                __half h = __float2half_rn(w4[i]);
                whx[qq][i] = __halves2half2(h, h);
            }
        } else {
            syq[qq] = sx;
            swy[qq][0] = w4[0]; swy[qq][1] = w4[1]; swy[qq][2] = w4[2]; swy[qq][3] = w4[3];
        }
    }
    __syncthreads();

    int ybase = syq[0];
    const __half2* ib = (const __half2*)(g_imgT + (size_t)b * 4096 * 256)
                        + (cg * 32 + cp);
    __half2* tcol = &tmp[q][0][cp];

    int sx = sxq[q];
    __half2 w0 = whx[q][0], w1 = whx[q][1], w2 = whx[q][2], w3 = whx[q][3];
    const __half2* base = ib + ((size_t)ybase * 64 + sx) * 128;

    #pragma unroll
    for (int y = 0; y < 20; y++) {
        const __half2* r = base + (size_t)y * 64 * 128;
        __half2 acc = __hmul2(r[0], w0);
        acc = __hfma2(r[128], w1, acc);
        acc = __hfma2(r[256], w2, acc);
        acc = __hfma2(r[384], w3, acc);
        tcol[y * 32] = acc;
    }

    __half* outn = g_roi + (size_t)n * KDIM + cg * 64 + 2 * cp;
    #pragma unroll
    for (int p = 0; p < 7; p++) {
        int sy = syq[p] - ybase;
        float v0 = swy[p][0], v1 = swy[p][1], v2 = swy[p][2], v3 = swy[p][3];
        float2 t0 = __half22float2(tcol[(sy + 0) * 32]);
        float2 t1 = __half22float2(tcol[(sy + 1) * 32]);
        float2 t2 = __half22float2(tcol[(sy + 2) * 32]);
        float2 t3 = __half22float2(tcol[(sy + 3) * 32]);
        float ax = fmaf(t3.x, v3, fmaf(t2.x, v2, fmaf(t1.x, v1, t0.x * v0)));
        float ay = fmaf(t3.y, v3, fmaf(t2.y, v2, fmaf(t1.y, v1, t0.y * v0)));
        *(__half2*)(outn + (p * 7 + q) * 256) = __floats2half2_rn(ax, ay);
    }
}

// ============================================================================
// Kernel B (pos v3): coalesced GEMV. grid=(64, 4), 256 thr. Initializes d_out.
// ============================================================================
__global__ __launch_bounds__(256) void pos_kernel(const float* __restrict__ boxes,
                                                  const float* __restrict__ cxw,
                                                  const float* __restrict__ cxb,
                                                  const float* __restrict__ pw,
                                                  const float* __restrict__ pb,
                                                  const float* __restrict__ convb,
                                                  float* __restrict__ out) {
    __shared__ __align__(16) float pet[258 * 4];
    __shared__ float bxv[4][4];
    int tid = threadIdx.x;
    int wid = tid >> 5, lane = tid & 31;
    int n0 = blockIdx.x * 4;
    int og = blockIdx.y;

    if (tid < 16) {
        int bxi = tid >> 2, e = tid & 3;
        float lo = boxes[(n0 + bxi) * 4 + (e & 1)];
        float hi = boxes[(n0 + bxi) * 4 + 2 + (e & 1)];
        bxv[bxi][e] = (e < 2) ? 0.5f * (lo + hi) : (hi - lo);
    }
    __syncthreads();

    #pragma unroll
    for (int j = 0; j < 5; j++) {
        int idx = tid + j * 256;
        if (idx < 1032) {
            int bxi = idx & 3;
            int k   = idx >> 2;
            float v;
            if (k >= 256) v = bxv[bxi][3 - (k - 256)];
            else {
                float coord = (k < 128) ? bxv[bxi][1] : bxv[bxi][0];
                int kk = k & 127;
                int m  = kk >> 1;
                float freq = exp2f(-(float)m * (13.287712379549449f / 64.0f));
                float pos  = coord * 6.283185307179586f * freq;
                v = (kk & 1) ? cosf(pos) : sinf(pos);
            }
            pet[k * 4 + bxi] = v;
        }
    }
    __syncthreads();

    int kb = lane * 8;
    #pragma unroll
    for (int i = 0; i < 8; i++) {
        int o = og * 64 + wid * 8 + i;
        const float* row = pw + (size_t)o * 258;
        float a0 = 0.f, a1 = 0.f, a2 = 0.f, a3 = 0.f;

        #pragma unroll
        for (int j = 0; j < 4; j++) {
            float2 w2 = *(const float2*)(row + kb + j * 2);
            float4 p0 = *(const float4*)(pet + (kb + j * 2) * 4);
            float4 p1 = *(const float4*)(pet + (kb + j * 2 + 1) * 4);
            a0 = fmaf(w2.x, p0.x, a0); a1 = fmaf(w2.x, p0.y, a1);
            a2 = fmaf(w2.x, p0.z, a2); a3 = fmaf(w2.x, p0.w, a3);
            a0 = fmaf(w2.y, p1.x, a0); a1 = fmaf(w2.y, p1.y, a1);
            a2 = fmaf(w2.y, p1.z, a2); a3 = fmaf(w2.y, p1.w, a3);
        }
        if (lane == 0) {
            float2 w2 = *(const float2*)(row + 256);
            float4 p0 = *(const float4*)(pet + 256 * 4);
            float4 p1 = *(const float4*)(pet + 257 * 4);
            a0 = fmaf(w2.x, p0.x, a0); a1 = fmaf(w2.x, p0.y, a1);
            a2 = fmaf(w2.x, p0.z, a2); a3 = fmaf(w2.x, p0.w, a3);
            a0 = fmaf(w2.y, p1.x, a0); a1 = fmaf(w2.y, p1.y, a1);
            a2 = fmaf(w2.y, p1.z, a2); a3 = fmaf(w2.y, p1.w, a3);
        }
        #pragma unroll
        for (int s = 16; s > 0; s >>= 1) {
            a0 += __shfl_xor_sync(0xFFFFFFFFu, a0, s);
            a1 += __shfl_xor_sync(0xFFFFFFFFu, a1, s);
            a2 += __shfl_xor_sync(0xFFFFFFFFu, a2, s);
            a3 += __shfl_xor_sync(0xFFFFFFFFu, a3, s);
        }
        if (lane == 0) {
            float base = pb[o] + cxb[o] + convb[o];
            float4 cw = *(const float4*)(cxw + o * 4);
            float r[4] = {a0, a1, a2, a3};
            #pragma unroll
            for (int bxi = 0; bxi < 4; bxi++)
                out[(size_t)(n0 + bxi) * CCH + o] = r[bxi] + base
                    + bxv[bxi][0] * cw.x + bxv[bxi][1] * cw.y
                    + bxv[bxi][2] * cw.z + bxv[bxi][3] * cw.w;
        }
    }
}

// ============================================================================
// Kernel C (R13-proven, + mhalf): fp16 mma.sync GEMM, 256 thr, 128x128,
// 3-stage cp.async + ldmatrix, GSPL=37. grid (1,2,37) per m-half.
// ============================================================================
#define GBK  32
#define GSPL 37
#define NKT  392
#define LDH  40
#define GSTAGE (128 * LDH)
#define GSMEM_BYTES (3 * GSTAGE * 2 * 2)

__global__ __launch_bounds__(256) void gemm_kernel(int mhalf) {
    extern __shared__ __align__(16) __half ghs[];
    __half* gA = ghs;
    __half* gB = ghs + 3 * GSTAGE;
    uint32_t sA = smem_u32(gA);
    uint32_t sB = smem_u32(gB);

    int tid = threadIdx.x;
    int wid = tid >> 5, lane = tid & 31;
    int m0 = mhalf * 128;
    int o0 = blockIdx.y * 128;
    int t0 = (blockIdx.z * NKT) / GSPL;
    int t1 = ((blockIdx.z + 1) * NKT) / GSPL;
    int nt = t1 - t0;
    int k0 = t0 * GBK;

    int wm = (wid >> 1) * 32;
    int wn = (wid & 1) * 64;
    int gID = lane >> 2;
    int tg  = lane & 3;

    uint32_t aoff = (uint32_t)((wm + ((lane >> 3) & 1) * 8 + (lane & 7)) * LDH
                               + (lane >> 4) * 8) * 2;
    uint32_t boff = (uint32_t)((wn + (lane >> 4) * 8 + (lane & 7)) * LDH
                               + ((lane >> 3) & 1) * 8) * 2;

    float acc[2][8][4];
    #pragma unroll
    for (int mi = 0; mi < 2; mi++)
        #pragma unroll
        for (int ni = 0; ni < 8; ni++)
            #pragma unroll
            for (int r = 0; r < 4; r++) acc[mi][ni][r] = 0.0f;

    auto issue = [&](int t, int st) {
        int kt = k0 + t * GBK;
        uint32_t dA = sA + (uint32_t)(st * GSTAGE) * 2;
        uint32_t dB = sB + (uint32_t)(st * GSTAGE) * 2;
        #pragma unroll
        for (int j = 0; j < 2; j++) {
            int i   = tid + j * 256;
            int row = i >> 2;
            int c8  = i & 3;
            uint32_t so = (uint32_t)(row * LDH + c8 * 8) * 2;
            cpasync16(dA + so, g_roi + (size_t)(m0 + row) * KDIM + kt + c8 * 8);
            cpasync16(dB + so, g_bh  + (size_t)(o0 + row) * KDIM + kt + c8 * 8);
        }
        CP_COMMIT();
    };

    issue(0, 0);
    issue(1, 1);

    for (int t = 0; t < nt; t++) {
        if (t < nt - 1) { CP_WAIT(1); } else { CP_WAIT(0); }
        __syncthreads();
        if (t + 2 < nt) issue(t + 2, (t + 2) % 3);

        int st = t % 3;
        uint32_t stA = sA + (uint32_t)(st * GSTAGE) * 2;
        uint32_t stB = sB + (uint32_t)(st * GSTAGE) * 2;

        #pragma unroll
        for (int ks = 0; ks < 2; ks++) {
            uint32_t kadd = (uint32_t)(ks * 16) * 2;
            uint32_t af[2][4];
            ldsm_x4(af[0], stA + aoff + kadd);
            ldsm_x4(af[1], stA + aoff + (uint32_t)(16 * LDH) * 2 + kadd);
            uint32_t bf[8][2];
            #pragma unroll
            for (int np = 0; np < 4; np++) {
                uint32_t bq[4];
                ldsm_x4(bq, stB + boff + (uint32_t)(np * 16 * LDH) * 2 + kadd);
                bf[2 * np][0]     = bq[0];
                bf[2 * np][1]     = bq[1];
                bf[2 * np + 1][0] = bq[2];
                bf[2 * np + 1][1] = bq[3];
            }
            #pragma unroll
            for (int mi = 0; mi < 2; mi++)
                #pragma unroll
                for (int ni = 0; ni < 8; ni++)
                    mma_f16(acc[mi][ni], af[mi], bf[ni]);
        }
    }

    float* pp = g_part + (size_t)blockIdx.z * 65536;
    #pragma unroll
    for (int mi = 0; mi < 2; mi++) {
        #pragma unroll
        for (int ni = 0; ni < 8; ni++) {
            int rbase = m0 + wm + mi * 16 + gID;
            int cbase = o0 + wn + ni * 8 + tg * 2;
            *(float2*)(pp + (size_t)rbase * CCH + cbase)       = make_float2(acc[mi][ni][0], acc[mi][ni][1]);
            *(float2*)(pp + (size_t)(rbase + 8) * CCH + cbase) = make_float2(acc[mi][ni][2], acc[mi][ni][3]);
        }
    }
}

// ============================================================================
// Kernel R: reduce 37 partial planes into d_out (float4, 128 CTAs)
// ============================================================================
__global__ __launch_bounds__(128) void reduce_kernel(float* __restrict__ out) {
    size_t i = ((size_t)blockIdx.x * 128 + threadIdx.x) * 4;
    float4 a = *(float4*)(out + i);
    #pragma unroll 7
    for (int s = 0; s < GSPL; s++) {
        float4 p = *(const float4*)(g_part + (size_t)s * 65536 + i);
        a.x += p.x; a.y += p.y; a.z += p.z; a.w += p.w;
    }
    *(float4*)(out + i) = a;
}

// ============================================================================
// Launcher: fork-join + box-split gemm overlap (capture-legal).
//   main: trans -> roi_a -> roi_b -> gemm_b -> reduce
//   s1:   convp -> [wait roi_a] gemm_a
//   s2:   pos
// ============================================================================
extern "C" void kernel_launch(void* const* d_in, const int* in_sizes, int n_in,
                              void* d_out, int out_size) {
    const float* img    = (const float*)d_in[0];
    const float* boxes  = (const float*)d_in[1];
    const float* conv_w = (const float*)d_in[2];
    const float* conv_b = (const float*)d_in[3];
    const float* cxw    = (const float*)d_in[4];
    const float* cxb    = (const float*)d_in[5];
    const float* pw     = (const float*)d_in[6];
    const float* pb     = (const float*)d_in[7];
    float* out = (float*)d_out;

    static cudaStream_t s1 = nullptr, s2 = nullptr;
    static cudaEvent_t ev0 = nullptr, ev1 = nullptr, ev2 = nullptr;
    static cudaEvent_t evA = nullptr, evG = nullptr;
    static bool init_done = false;
    if (!init_done) {
        cudaFuncSetAttribute(gemm_kernel, cudaFuncAttributeMaxDynamicSharedMemorySize,
                             GSMEM_BYTES);
        cudaStreamCreateWithFlags(&s1, cudaStreamNonBlocking);
        cudaStreamCreateWithFlags(&s2, cudaStreamNonBlocking);
        cudaEventCreateWithFlags(&ev0, cudaEventDisableTiming);
        cudaEventCreateWithFlags(&ev1, cudaEventDisableTiming);
        cudaEventCreateWithFlags(&ev2, cudaEventDisableTiming);
        cudaEventCreateWithFlags(&evA, cudaEventDisableTiming);
        cudaEventCreateWithFlags(&evG, cudaEventDisableTiming);
        init_done = true;
    }

    // fork
    cudaEventRecord(ev0, 0);
    cudaStreamWaitEvent(s1, ev0, 0);
    cudaStreamWaitEvent(s2, ev0, 0);

    // side branches
    convp_kernel<<<256, 128, 0, s1>>>(conv_w);
    cudaEventRecord(ev1, s1);
    pos_kernel<<<dim3(64, 4), 256, 0, s2>>>(boxes, cxw, cxb, pw, pb, conv_b, out);
    cudaEventRecord(ev2, s2);

    // main chain
    trans_kernel<<<dim3(64, 4, 4), 256>>>(img);
    roi_kernel<<<dim3(128, 4), 224>>>(boxes, 0);       // boxes 0..127
    cudaEventRecord(evA, 0);

    // gemm_a overlaps roi_b on s1 (s1 already ordered after convp)
    cudaStreamWaitEvent(s1, evA, 0);
    dim3 ggrid(1, 2, GSPL);
    gemm_kernel<<<ggrid, 256, GSMEM_BYTES, s1>>>(0);
    cudaEventRecord(evG, s1);

    roi_kernel<<<dim3(128, 4), 224>>>(boxes, 128);     // boxes 128..255

    cudaStreamWaitEvent(0, ev1, 0);          // gemm_b needs convp
    gemm_kernel<<<ggrid, 256, GSMEM_BYTES>>>(1);

    cudaStreamWaitEvent(0, evG, 0);          // reduce needs gemm_a
    cudaStreamWaitEvent(0, ev2, 0);          // reduce needs pos
    reduce_kernel<<<128, 128>>>(out);
}

// round 16
// speedup vs baseline: 1.4781x; 1.4781x over previous
#include <cuda_runtime.h>
#include <cuda_fp16.h>
#include <stdint.h>
#include <math.h>

#define NTOT 256
#define CCH  256
#define KDIM 12544

__device__ __half g_roi [(size_t)NTOT * KDIM];      // A matrix, k = pq*256 + c
__device__ __half g_bh  [(size_t)CCH  * KDIM];      // conv_w fp16, k = pq*256 + c
__device__ __half g_imgT[(size_t)4 * 4096 * 256];   // image [b][y*64+x][c] fp16
__device__ float  g_part[(size_t)37 * 65536];       // split-K partials
__device__ unsigned g_bar;                          // sw grid barrier (monotone)

// ============================================================================
// helpers
// ============================================================================
__device__ __forceinline__ uint32_t smem_u32(const void* p) {
    uint32_t a;
    asm("{ .reg .u64 t; cvta.to.shared.u64 t, %1; cvt.u32.u64 %0, t; }"
        : "=r"(a) : "l"(p));
    return a;
}
__device__ __forceinline__ void cpasync16(uint32_t dst, const void* src) {
    asm volatile("cp.async.cg.shared.global [%0], [%1], 16;" :: "r"(dst), "l"(src));
}
#define CP_COMMIT() asm volatile("cp.async.commit_group;" ::: "memory")
#define CP_WAIT(n)  asm volatile("cp.async.wait_group %0;" :: "n"(n) : "memory")

__device__ __forceinline__ void mma_f16(float c[4], const uint32_t a[4], const uint32_t b[2]) {
    asm volatile(
        "mma.sync.aligned.m16n8k16.row.col.f32.f16.f16.f32 "
        "{%0,%1,%2,%3}, {%4,%5,%6,%7}, {%8,%9}, {%0,%1,%2,%3};"
        : "+f"(c[0]), "+f"(c[1]), "+f"(c[2]), "+f"(c[3])
        : "r"(a[0]), "r"(a[1]), "r"(a[2]), "r"(a[3]), "r"(b[0]), "r"(b[1]));
}
__device__ __forceinline__ void ldsm_x4(uint32_t r[4], uint32_t addr) {
    asm volatile("ldmatrix.sync.aligned.m8n8.x4.shared.b16 {%0,%1,%2,%3}, [%4];"
        : "=r"(r[0]), "=r"(r[1]), "=r"(r[2]), "=r"(r[3]) : "r"(addr));
}

// ============================================================================
// Kernel 1 (prep): trans (blocks 0..1023) U convp (1024..1279) U pos (1280..1535)
// 256 threads. Shared memory reused via a char arena (max user = convp 25088 B).
// ============================================================================
__global__ __launch_bounds__(256) void prep_kernel(const float* __restrict__ img,
                                                   const float* __restrict__ conv_w,
                                                   const float* __restrict__ boxes,
                                                   const float* __restrict__ cxw,
                                                   const float* __restrict__ cxb,
                                                   const float* __restrict__ pw,
                                                   const float* __restrict__ pb,
                                                   const float* __restrict__ convb,
                                                   float* __restrict__ out) {
    __shared__ __align__(16) char usm[25088];
    int blk = blockIdx.x;
    int tid = threadIdx.x;

    if (blk < 1024) {
        // ---------------- trans: img [b][c][yx] fp32 -> g_imgT [b][yx][c] fp16
        float* tile = (float*)usm;              // [64][65]
        int yx0 = (blk & 63) * 64;
        int c0  = ((blk >> 6) & 3) * 64;
        int b   = blk >> 8;
        const float* src = img + ((size_t)b * 256 + c0) * 4096 + yx0;
        #pragma unroll
        for (int j = 0; j < 16; j++) {
            int idx = tid + j * 256;
            int row = idx >> 6, col = idx & 63;
            tile[row * 65 + col] = src[(size_t)row * 4096 + col];
        }
        __syncthreads();
        #pragma unroll
        for (int pass = 0; pass < 2; pass++) {
            int tt = tid + pass * 256;
            int w = tt >> 3, cc = (tt & 7) * 8;
            __half2 h0 = __floats2half2_rn(tile[(cc + 0) * 65 + w], tile[(cc + 1) * 65 + w]);
            __half2 h1 = __floats2half2_rn(tile[(cc + 2) * 65 + w], tile[(cc + 3) * 65 + w]);
            __half2 h2 = __floats2half2_rn(tile[(cc + 4) * 65 + w], tile[(cc + 5) * 65 + w]);
            __half2 h3 = __floats2half2_rn(tile[(cc + 6) * 65 + w], tile[(cc + 7) * 65 + w]);
            uint4 u;
            u.x = *(uint32_t*)&h0; u.y = *(uint32_t*)&h1;
            u.z = *(uint32_t*)&h2; u.w = *(uint32_t*)&h3;
            *(uint4*)(g_imgT + ((size_t)b * 4096 + yx0 + w) * 256 + c0 + cc) = u;
        }
    } else if (blk < 1280) {
        // ---------------- convp: conv_w [o][c][pq] fp32 -> g_bh [o][pq*256+c] fp16
        float* buf = (float*)usm;               // 128*49 floats
        int o = blk - 1024;
        #pragma unroll
        for (int h = 0; h < 2; h++) {
            const float* src = conv_w + (size_t)o * KDIM + h * 128 * 49;
            if (tid < 128) {
                #pragma unroll
                for (int j = 0; j < 49; j++) buf[j * 128 + tid] = src[j * 128 + tid];
            }
            __syncthreads();
            if (tid < 128) {
                __half* dst = g_bh + (size_t)o * KDIM + h * 128 + tid;
                #pragma unroll
                for (int j = 0; j < 49; j++)
                    dst[j * 256] = __float2half_rn(buf[tid * 49 + j]);
            }
            __syncthreads();
        }
    } else {
        // ---------------- pos: base + posenc GEMV, initializes d_out
        float* pet = (float*)usm;               // 258*4 floats
        float (*bxv)[4] = (float(*)[4])(pet + 1032);
        int pb2 = blk - 1280;
        int n0 = (pb2 & 63) * 4;
        int og = pb2 >> 6;
        int wid = tid >> 5, lane = tid & 31;

        if (tid < 16) {
            int bxi = tid >> 2, e = tid & 3;
            float lo = boxes[(n0 + bxi) * 4 + (e & 1)];
            float hi = boxes[(n0 + bxi) * 4 + 2 + (e & 1)];
            bxv[bxi][e] = (e < 2) ? 0.5f * (lo + hi) : (hi - lo);
        }
        __syncthreads();

        #pragma unroll
        for (int j = 0; j < 5; j++) {
            int idx = tid + j * 256;
            if (idx < 1032) {
                int bxi = idx & 3;
                int k   = idx >> 2;
                float v;
                if (k >= 256) v = bxv[bxi][3 - (k - 256)];
                else {
                    float coord = (k < 128) ? bxv[bxi][1] : bxv[bxi][0];
                    int kk = k & 127;
                    int m  = kk >> 1;
                    float freq = exp2f(-(float)m * (13.287712379549449f / 64.0f));
                    float pos  = coord * 6.283185307179586f * freq;
                    v = (kk & 1) ? cosf(pos) : sinf(pos);
                }
                pet[k * 4 + bxi] = v;
            }
        }
        __syncthreads();

        int kb = lane * 8;
        #pragma unroll
        for (int i = 0; i < 8; i++) {
            int o = og * 64 + wid * 8 + i;
            const float* row = pw + (size_t)o * 258;
            float a0 = 0.f, a1 = 0.f, a2 = 0.f, a3 = 0.f;
            #pragma unroll
            for (int j = 0; j < 4; j++) {
                float2 w2 = *(const float2*)(row + kb + j * 2);
                float4 p0 = *(const float4*)(pet + (kb + j * 2) * 4);
                float4 p1 = *(const float4*)(pet + (kb + j * 2 + 1) * 4);
                a0 = fmaf(w2.x, p0.x, a0); a1 = fmaf(w2.x, p0.y, a1);
                a2 = fmaf(w2.x, p0.z, a2); a3 = fmaf(w2.x, p0.w, a3);
                a0 = fmaf(w2.y, p1.x, a0); a1 = fmaf(w2.y, p1.y, a1);
                a2 = fmaf(w2.y, p1.z, a2); a3 = fmaf(w2.y, p1.w, a3);
            }
            if (lane == 0) {
                float2 w2 = *(const float2*)(row + 256);
                float4 p0 = *(const float4*)(pet + 256 * 4);
                float4 p1 = *(const float4*)(pet + 257 * 4);
                a0 = fmaf(w2.x, p0.x, a0); a1 = fmaf(w2.x, p0.y, a1);
                a2 = fmaf(w2.x, p0.z, a2); a3 = fmaf(w2.x, p0.w, a3);
                a0 = fmaf(w2.y, p1.x, a0); a1 = fmaf(w2.y, p1.y, a1);
                a2 = fmaf(w2.y, p1.z, a2); a3 = fmaf(w2.y, p1.w, a3);
            }
            #pragma unroll
            for (int s = 16; s > 0; s >>= 1) {
                a0 += __shfl_xor_sync(0xFFFFFFFFu, a0, s);
                a1 += __shfl_xor_sync(0xFFFFFFFFu, a1, s);
                a2 += __shfl_xor_sync(0xFFFFFFFFu, a2, s);
                a3 += __shfl_xor_sync(0xFFFFFFFFu, a3, s);
            }
            if (lane == 0) {
                float base = pb[o] + cxb[o] + convb[o];
                float4 cw = *(const float4*)(cxw + o * 4);
                float r[4] = {a0, a1, a2, a3};
                #pragma unroll
                for (int bxi = 0; bxi < 4; bxi++)
                    out[(size_t)(n0 + bxi) * CCH + o] = r[bxi] + base
                        + bxv[bxi][0] * cw.x + bxv[bxi][1] * cw.y
                        + bxv[bxi][2] * cw.z + bxv[bxi][3] * cw.w;
            }
        }
    }
}

// ============================================================================
// Kernel 2 (roi v6, committed): grid (256,4), block 224 = 7q x 32cp.
// ============================================================================
__global__ __launch_bounds__(224) void roi_kernel(const float* __restrict__ boxes) {
    __shared__ __half2 whx[7][4];
    __shared__ float   swy[7][4];
    __shared__ int     sxq[7], syq[7];
    __shared__ __half2 tmp[7][20][32];

    int n   = blockIdx.x;
    int cg  = blockIdx.y;
    int b   = n >> 6;
    int tid = threadIdx.x;
    int cp  = tid & 31;
    int q   = tid >> 5;

    if (tid < 14) {
        int qq = tid >> 1, axis = tid & 1;
        const float nsc = 64.0f / 63.0f;
        float lo = boxes[n * 4 + axis]     * nsc;
        float hi = boxes[n * 4 + 2 + axis] * nsc;
        float span = hi - lo;
        float hs = span * (1.0f / 42.0f);
        float w4[4] = {0.f, 0.f, 0.f, 0.f};
        int sx = 0;
        #pragma unroll
        for (int s = 0; s < 3; s++) {
            int i = qq * 3 + s;
            float t = (float)i * (1.0f / 20.0f);
            float gg = lo + hs + t * (span - 2.0f * hs);
            float p = gg * 63.0f;
            float f = floorf(p);
            int x0 = (int)f;
            float w = p - f;
            if (s == 0) sx = x0;
            int d = x0 - sx;
            w4[d]     += (1.0f - w) * (1.0f / 3.0f);
            w4[d + 1] += w * (1.0f / 3.0f);
        }
        if (axis == 0) {
            sxq[qq] = sx;
            #pragma unroll
            for (int i = 0; i < 4; i++) {
                __half h = __float2half_rn(w4[i]);
                whx[qq][i] = __halves2half2(h, h);
            }
        } else {
            syq[qq] = sx;
            swy[qq][0] = w4[0]; swy[qq][1] = w4[1]; swy[qq][2] = w4[2]; swy[qq][3] = w4[3];
        }
    }
    __syncthreads();

    int ybase = syq[0];
    const __half2* ib = (const __half2*)(g_imgT + (size_t)b * 4096 * 256)
                        + (cg * 32 + cp);
    __half2* tcol = &tmp[q][0][cp];

    int sx = sxq[q];
    __half2 w0 = whx[q][0], w1 = whx[q][1], w2 = whx[q][2], w3 = whx[q][3];
    const __half2* base = ib + ((size_t)ybase * 64 + sx) * 128;

    #pragma unroll
    for (int y = 0; y < 20; y++) {
        const __half2* r = base + (size_t)y * 64 * 128;
        __half2 acc = __hmul2(r[0], w0);
        acc = __hfma2(r[128], w1, acc);
        acc = __hfma2(r[256], w2, acc);
        acc = __hfma2(r[384], w3, acc);
        tcol[y * 32] = acc;
    }

    __half* outn = g_roi + (size_t)n * KDIM + cg * 64 + 2 * cp;
    #pragma unroll
    for (int p = 0; p < 7; p++) {
        int sy = syq[p] - ybase;
        float v0 = swy[p][0], v1 = swy[p][1], v2 = swy[p][2], v3 = swy[p][3];
        float2 t0 = __half22float2(tcol[(sy + 0) * 32]);
        float2 t1 = __half22float2(tcol[(sy + 1) * 32]);
        float2 t2 = __half22float2(tcol[(sy + 2) * 32]);
        float2 t3 = __half22float2(tcol[(sy + 3) * 32]);
        float ax = fmaf(t3.x, v3, fmaf(t2.x, v2, fmaf(t1.x, v1, t0.x * v0)));
        float ay = fmaf(t3.y, v3, fmaf(t2.y, v2, fmaf(t1.y, v1, t0.y * v0)));
        *(__half2*)(outn + (p * 7 + q) * 256) = __floats2half2_rn(ax, ay);
    }
}

// ============================================================================
// Kernel 3: R13 gemm (148 CTAs, 1/SM guaranteed resident) + sw grid barrier
// (epoch-safe monotone counter) + fused reduce into d_out.
// ============================================================================
#define GBK  32
#define GSPL 37
#define NKT  392
#define LDH  40
#define GSTAGE (128 * LDH)
#define GSMEM_BYTES (3 * GSTAGE * 2 * 2)

__global__ __launch_bounds__(256) void gemm_reduce_kernel(float* __restrict__ out) {
    extern __shared__ __align__(16) __half ghs[];
    __half* gA = ghs;
    __half* gB = ghs + 3 * GSTAGE;
    uint32_t sA = smem_u32(gA);
    uint32_t sB = smem_u32(gB);

    int tid = threadIdx.x;
    int wid = tid >> 5, lane = tid & 31;
    int m0 = blockIdx.x * 128;
    int o0 = blockIdx.y * 128;
    int t0 = (blockIdx.z * NKT) / GSPL;
    int t1 = ((blockIdx.z + 1) * NKT) / GSPL;
    int nt = t1 - t0;
    int k0 = t0 * GBK;

    int wm = (wid >> 1) * 32;
    int wn = (wid & 1) * 64;
    int gID = lane >> 2;
    int tg  = lane & 3;

    uint32_t aoff = (uint32_t)((wm + ((lane >> 3) & 1) * 8 + (lane & 7)) * LDH
                               + (lane >> 4) * 8) * 2;
    uint32_t boff = (uint32_t)((wn + (lane >> 4) * 8 + (lane & 7)) * LDH
                               + ((lane >> 3) & 1) * 8) * 2;

    float acc[2][8][4];
    #pragma unroll
    for (int mi = 0; mi < 2; mi++)
        #pragma unroll
        for (int ni = 0; ni < 8; ni++)
            #pragma unroll
            for (int r = 0; r < 4; r++) acc[mi][ni][r] = 0.0f;

    auto issue = [&](int t, int st) {
        int kt = k0 + t * GBK;
        uint32_t dA = sA + (uint32_t)(st * GSTAGE) * 2;
        uint32_t dB = sB + (uint32_t)(st * GSTAGE) * 2;
        #pragma unroll
        for (int j = 0; j < 2; j++) {
            int i   = tid + j * 256;
            int row = i >> 2;
            int c8  = i & 3;
            uint32_t so = (uint32_t)(row * LDH + c8 * 8) * 2;
            cpasync16(dA + so, g_roi + (size_t)(m0 + row) * KDIM + kt + c8 * 8);
            cpasync16(dB + so, g_bh  + (size_t)(o0 + row) * KDIM + kt + c8 * 8);
        }
        CP_COMMIT();
    };

    issue(0, 0);
    issue(1, 1);

    for (int t = 0; t < nt; t++) {
        if (t < nt - 1) { CP_WAIT(1); } else { CP_WAIT(0); }
        __syncthreads();
        if (t + 2 < nt) issue(t + 2, (t + 2) % 3);

        int st = t % 3;
        uint32_t stA = sA + (uint32_t)(st * GSTAGE) * 2;
        uint32_t stB = sB + (uint32_t)(st * GSTAGE) * 2;

        #pragma unroll
        for (int ks = 0; ks < 2; ks++) {
            uint32_t kadd = (uint32_t)(ks * 16) * 2;
            uint32_t af[2][4];
            ldsm_x4(af[0], stA + aoff + kadd);
            ldsm_x4(af[1], stA + aoff + (uint32_t)(16 * LDH) * 2 + kadd);
            uint32_t bf[8][2];
            #pragma unroll
            for (int np = 0; np < 4; np++) {
                uint32_t bq[4];
                ldsm_x4(bq, stB + boff + (uint32_t)(np * 16 * LDH) * 2 + kadd);
                bf[2 * np][0]     = bq[0];
                bf[2 * np][1]     = bq[1];
                bf[2 * np + 1][0] = bq[2];
                bf[2 * np + 1][1] = bq[3];
            }
            #pragma unroll
            for (int mi = 0; mi < 2; mi++)
                #pragma unroll
                for (int ni = 0; ni < 8; ni++)
                    mma_f16(acc[mi][ni], af[mi], bf[ni]);
        }
    }

    float* pp = g_part + (size_t)blockIdx.z * 65536;
    #pragma unroll
    for (int mi = 0; mi < 2; mi++) {
        #pragma unroll
        for (int ni = 0; ni < 8; ni++) {
            int rbase = m0 + wm + mi * 16 + gID;
            int cbase = o0 + wn + ni * 8 + tg * 2;
            *(float2*)(pp + (size_t)rbase * CCH + cbase)       = make_float2(acc[mi][ni][0], acc[mi][ni][1]);
            *(float2*)(pp + (size_t)(rbase + 8) * CCH + cbase) = make_float2(acc[mi][ni][2], acc[mi][ni][3]);
        }
    }

    // ---- software grid barrier (all 148 CTAs are resident: 1/SM) ----
    __threadfence();
    __syncthreads();
    if (tid == 0) {
        unsigned a = atomicAdd(&g_bar, 1u);          // epoch-monotone
        unsigned tgt = (a / 148u + 1u) * 148u;
        while (*(volatile unsigned*)&g_bar < tgt) { }
        __threadfence();
    }
    __syncthreads();

    // ---- fused reduce: one float4 per thread (16384 total, 37888 threads) ----
    int flat = blockIdx.x + (blockIdx.y << 1) + (blockIdx.z << 2);
    int idx = flat * 256 + tid;
    if (idx < 16384) {
        size_t i = (size_t)idx * 4;
        float4 a = *(float4*)(out + i);
        #pragma unroll 7
        for (int s = 0; s < GSPL; s++) {
            float4 p = *(const float4*)(g_part + (size_t)s * 65536 + i);
            a.x += p.x; a.y += p.y; a.z += p.z; a.w += p.w;
        }
        *(float4*)(out + i) = a;
    }
}

// ============================================================================
// Launcher: 3 kernels, one stream, no events.
// ============================================================================
extern "C" void kernel_launch(void* const* d_in, const int* in_sizes, int n_in,
                              void* d_out, int out_size) {
    const float* img    = (const float*)d_in[0];
    const float* boxes  = (const float*)d_in[1];
    const float* conv_w = (const float*)d_in[2];
    const float* conv_b = (const float*)d_in[3];
    const float* cxw    = (const float*)d_in[4];
    const float* cxb    = (const float*)d_in[5];
    const float* pw     = (const float*)d_in[6];
    const float* pb     = (const float*)d_in[7];
    float* out = (float*)d_out;

    static bool init_done = false;
    if (!init_done) {
        cudaFuncSetAttribute(gemm_reduce_kernel,
                             cudaFuncAttributeMaxDynamicSharedMemorySize, GSMEM_BYTES);
        init_done = true;
    }

    prep_kernel<<<1536, 256>>>(img, conv_w, boxes, cxw, cxb, pw, pb, conv_b, out);
    roi_kernel<<<dim3(256, 4), 224>>>(boxes);
    dim3 ggrid(2, 2, GSPL);
    gemm_reduce_kernel<<<ggrid, 256, GSMEM_BYTES>>>(out);
}

// round 17
// speedup vs baseline: 1.5813x; 1.0698x over previous
#include <cuda_runtime.h>
#include <cuda_fp16.h>
#include <stdint.h>
#include <math.h>

#define NTOT 256
#define CCH  256
#define KDIM 12544

__device__ __half g_roi [(size_t)NTOT * KDIM];      // A matrix, k = pq*256 + c
__device__ __half g_bh  [(size_t)CCH  * KDIM];      // conv_w fp16, k = pq*256 + c
__device__ __half g_imgT[(size_t)4 * 4096 * 256];   // image [b][y*64+x][c] fp16
__device__ float  g_part[(size_t)37 * 65536];       // split-K partials
__device__ unsigned g_bar;                          // sw grid barrier (monotone)

// ============================================================================
// helpers
// ============================================================================
__device__ __forceinline__ uint32_t smem_u32(const void* p) {
    uint32_t a;
    asm("{ .reg .u64 t; cvta.to.shared.u64 t, %1; cvt.u32.u64 %0, t; }"
        : "=r"(a) : "l"(p));
    return a;
}
__device__ __forceinline__ void cpasync16(uint32_t dst, const void* src) {
    asm volatile("cp.async.cg.shared.global [%0], [%1], 16;" :: "r"(dst), "l"(src));
}
#define CP_COMMIT() asm volatile("cp.async.commit_group;" ::: "memory")
#define CP_WAIT(n)  asm volatile("cp.async.wait_group %0;" :: "n"(n) : "memory")

__device__ __forceinline__ void mma_f16(float c[4], const uint32_t a[4], const uint32_t b[2]) {
    asm volatile(
        "mma.sync.aligned.m16n8k16.row.col.f32.f16.f16.f32 "
        "{%0,%1,%2,%3}, {%4,%5,%6,%7}, {%8,%9}, {%0,%1,%2,%3};"
        : "+f"(c[0]), "+f"(c[1]), "+f"(c[2]), "+f"(c[3])
        : "r"(a[0]), "r"(a[1]), "r"(a[2]), "r"(a[3]), "r"(b[0]), "r"(b[1]));
}
__device__ __forceinline__ void ldsm_x4(uint32_t r[4], uint32_t addr) {
    asm volatile("ldmatrix.sync.aligned.m8n8.x4.shared.b16 {%0,%1,%2,%3}, [%4];"
        : "=r"(r[0]), "=r"(r[1]), "=r"(r[2]), "=r"(r[3]) : "r"(addr));
}

// ============================================================================
// Kernel T: transpose img [b][c][yx] fp32 -> g_imgT [b][yx][c] fp16
// ============================================================================
__global__ __launch_bounds__(256) void trans_kernel(const float* __restrict__ img) {
    __shared__ float tile[64][65];
    int yx0 = blockIdx.x * 64, c0 = blockIdx.y * 64, b = blockIdx.z;
    int tid = threadIdx.x;
    const float* src = img + ((size_t)b * 256 + c0) * 4096 + yx0;
    #pragma unroll
    for (int j = 0; j < 16; j++) {
        int idx = tid + j * 256;
        int row = idx >> 6, col = idx & 63;
        tile[row][col] = src[(size_t)row * 4096 + col];
    }
    __syncthreads();
    #pragma unroll
    for (int pass = 0; pass < 2; pass++) {
        int tt = tid + pass * 256;
        int w = tt >> 3, cc = (tt & 7) * 8;
        __half2 h0 = __floats2half2_rn(tile[cc + 0][w], tile[cc + 1][w]);
        __half2 h1 = __floats2half2_rn(tile[cc + 2][w], tile[cc + 3][w]);
        __half2 h2 = __floats2half2_rn(tile[cc + 4][w], tile[cc + 5][w]);
        __half2 h3 = __floats2half2_rn(tile[cc + 6][w], tile[cc + 7][w]);
        uint4 u;
        u.x = *(uint32_t*)&h0; u.y = *(uint32_t*)&h1;
        u.z = *(uint32_t*)&h2; u.w = *(uint32_t*)&h3;
        *(uint4*)(g_imgT + ((size_t)b * 4096 + yx0 + w) * 256 + c0 + cc) = u;
    }
}

// ============================================================================
// Kernel P: permute+convert conv_w [o][c][pq] fp32 -> g_bh [o][pq*256+c] fp16
// ============================================================================
__global__ __launch_bounds__(128) void convp_kernel(const float* __restrict__ w) {
    __shared__ float buf[128 * 49];
    int o = blockIdx.x, tid = threadIdx.x;
    #pragma unroll
    for (int h = 0; h < 2; h++) {
        const float* src = w + (size_t)o * KDIM + h * 128 * 49;
        #pragma unroll
        for (int j = 0; j < 49; j++) buf[j * 128 + tid] = src[j * 128 + tid];
        __syncthreads();
        __half* dst = g_bh + (size_t)o * KDIM + h * 128 + tid;
        #pragma unroll
        for (int j = 0; j < 49; j++)
            dst[j * 256] = __float2half_rn(buf[tid * 49 + j]);
        __syncthreads();
    }
}

// ============================================================================
// Kernel A (roi v6, committed): grid (256,4), block 224 = 7q x 32cp.
// ============================================================================
__global__ __launch_bounds__(224) void roi_kernel(const float* __restrict__ boxes) {
    __shared__ __half2 whx[7][4];
    __shared__ float   swy[7][4];
    __shared__ int     sxq[7], syq[7];
    __shared__ __half2 tmp[7][20][32];

    int n   = blockIdx.x;
    int cg  = blockIdx.y;
    int b   = n >> 6;
    int tid = threadIdx.x;
    int cp  = tid & 31;
    int q   = tid >> 5;

    if (tid < 14) {
        int qq = tid >> 1, axis = tid & 1;
        const float nsc = 64.0f / 63.0f;
        float lo = boxes[n * 4 + axis]     * nsc;
        float hi = boxes[n * 4 + 2 + axis] * nsc;
        float span = hi - lo;
        float hs = span * (1.0f / 42.0f);
        float w4[4] = {0.f, 0.f, 0.f, 0.f};
        int sx = 0;
        #pragma unroll
        for (int s = 0; s < 3; s++) {
            int i = qq * 3 + s;
            float t = (float)i * (1.0f / 20.0f);
            float gg = lo + hs + t * (span - 2.0f * hs);
            float p = gg * 63.0f;
            float f = floorf(p);
            int x0 = (int)f;
            float w = p - f;
            if (s == 0) sx = x0;
            int d = x0 - sx;
            w4[d]     += (1.0f - w) * (1.0f / 3.0f);
            w4[d + 1] += w * (1.0f / 3.0f);
        }
        if (axis == 0) {
            sxq[qq] = sx;
            #pragma unroll
            for (int i = 0; i < 4; i++) {
                __half h = __float2half_rn(w4[i]);
                whx[qq][i] = __halves2half2(h, h);
            }
        } else {
            syq[qq] = sx;
            swy[qq][0] = w4[0]; swy[qq][1] = w4[1]; swy[qq][2] = w4[2]; swy[qq][3] = w4[3];
        }
    }
    __syncthreads();

    int ybase = syq[0];
    const __half2* ib = (const __half2*)(g_imgT + (size_t)b * 4096 * 256)
                        + (cg * 32 + cp);
    __half2* tcol = &tmp[q][0][cp];

    int sx = sxq[q];
    __half2 w0 = whx[q][0], w1 = whx[q][1], w2 = whx[q][2], w3 = whx[q][3];
    const __half2* base = ib + ((size_t)ybase * 64 + sx) * 128;

    #pragma unroll
    for (int y = 0; y < 20; y++) {
        const __half2* r = base + (size_t)y * 64 * 128;
        __half2 acc = __hmul2(r[0], w0);
        acc = __hfma2(r[128], w1, acc);
        acc = __hfma2(r[256], w2, acc);
        acc = __hfma2(r[384], w3, acc);
        tcol[y * 32] = acc;
    }

    __half* outn = g_roi + (size_t)n * KDIM + cg * 64 + 2 * cp;
    #pragma unroll
    for (int p = 0; p < 7; p++) {
        int sy = syq[p] - ybase;
        float v0 = swy[p][0], v1 = swy[p][1], v2 = swy[p][2], v3 = swy[p][3];
        float2 t0 = __half22float2(tcol[(sy + 0) * 32]);
        float2 t1 = __half22float2(tcol[(sy + 1) * 32]);
        float2 t2 = __half22float2(tcol[(sy + 2) * 32]);
        float2 t3 = __half22float2(tcol[(sy + 3) * 32]);
        float ax = fmaf(t3.x, v3, fmaf(t2.x, v2, fmaf(t1.x, v1, t0.x * v0)));
        float ay = fmaf(t3.y, v3, fmaf(t2.y, v2, fmaf(t1.y, v1, t0.y * v0)));
        *(__half2*)(outn + (p * 7 + q) * 256) = __floats2half2_rn(ax, ay);
    }
}

// ============================================================================
// Kernel B (pos v3): coalesced GEMV. grid=(64, 4), 256 thr. Initializes d_out.
// ============================================================================
__global__ __launch_bounds__(256) void pos_kernel(const float* __restrict__ boxes,
                                                  const float* __restrict__ cxw,
                                                  const float* __restrict__ cxb,
                                                  const float* __restrict__ pw,
                                                  const float* __restrict__ pb,
                                                  const float* __restrict__ convb,
                                                  float* __restrict__ out) {
    __shared__ __align__(16) float pet[258 * 4];
    __shared__ float bxv[4][4];
    int tid = threadIdx.x;
    int wid = tid >> 5, lane = tid & 31;
    int n0 = blockIdx.x * 4;
    int og = blockIdx.y;

    if (tid < 16) {
        int bxi = tid >> 2, e = tid & 3;
        float lo = boxes[(n0 + bxi) * 4 + (e & 1)];
        float hi = boxes[(n0 + bxi) * 4 + 2 + (e & 1)];
        bxv[bxi][e] = (e < 2) ? 0.5f * (lo + hi) : (hi - lo);
    }
    __syncthreads();

    #pragma unroll
    for (int j = 0; j < 5; j++) {
        int idx = tid + j * 256;
        if (idx < 1032) {
            int bxi = idx & 3;
            int k   = idx >> 2;
            float v;
            if (k >= 256) v = bxv[bxi][3 - (k - 256)];
            else {
                float coord = (k < 128) ? bxv[bxi][1] : bxv[bxi][0];
                int kk = k & 127;
                int m  = kk >> 1;
                float freq = exp2f(-(float)m * (13.287712379549449f / 64.0f));
                float pos  = coord * 6.283185307179586f * freq;
                v = (kk & 1) ? cosf(pos) : sinf(pos);
            }
            pet[k * 4 + bxi] = v;
        }
    }
    __syncthreads();

    int kb = lane * 8;
    #pragma unroll
    for (int i = 0; i < 8; i++) {
        int o = og * 64 + wid * 8 + i;
        const float* row = pw + (size_t)o * 258;
        float a0 = 0.f, a1 = 0.f, a2 = 0.f, a3 = 0.f;

        #pragma unroll
        for (int j = 0; j < 4; j++) {
            float2 w2 = *(const float2*)(row + kb + j * 2);
            float4 p0 = *(const float4*)(pet + (kb + j * 2) * 4);
            float4 p1 = *(const float4*)(pet + (kb + j * 2 + 1) * 4);
            a0 = fmaf(w2.x, p0.x, a0); a1 = fmaf(w2.x, p0.y, a1);
            a2 = fmaf(w2.x, p0.z, a2); a3 = fmaf(w2.x, p0.w, a3);
            a0 = fmaf(w2.y, p1.x, a0); a1 = fmaf(w2.y, p1.y, a1);
            a2 = fmaf(w2.y, p1.z, a2); a3 = fmaf(w2.y, p1.w, a3);
        }
        if (lane == 0) {
            float2 w2 = *(const float2*)(row + 256);
            float4 p0 = *(const float4*)(pet + 256 * 4);
            float4 p1 = *(const float4*)(pet + 257 * 4);
            a0 = fmaf(w2.x, p0.x, a0); a1 = fmaf(w2.x, p0.y, a1);
            a2 = fmaf(w2.x, p0.z, a2); a3 = fmaf(w2.x, p0.w, a3);
            a0 = fmaf(w2.y, p1.x, a0); a1 = fmaf(w2.y, p1.y, a1);
            a2 = fmaf(w2.y, p1.z, a2); a3 = fmaf(w2.y, p1.w, a3);
        }
        #pragma unroll
        for (int s = 16; s > 0; s >>= 1) {
            a0 += __shfl_xor_sync(0xFFFFFFFFu, a0, s);
            a1 += __shfl_xor_sync(0xFFFFFFFFu, a1, s);
            a2 += __shfl_xor_sync(0xFFFFFFFFu, a2, s);
            a3 += __shfl_xor_sync(0xFFFFFFFFu, a3, s);
        }
        if (lane == 0) {
            float base = pb[o] + cxb[o] + convb[o];
            float4 cw = *(const float4*)(cxw + o * 4);
            float r[4] = {a0, a1, a2, a3};
            #pragma unroll
            for (int bxi = 0; bxi < 4; bxi++)
                out[(size_t)(n0 + bxi) * CCH + o] = r[bxi] + base
                    + bxv[bxi][0] * cw.x + bxv[bxi][1] * cw.y
                    + bxv[bxi][2] * cw.z + bxv[bxi][3] * cw.w;
        }
    }
}

// ============================================================================
// Kernel C: R13 gemm (148 CTAs = 1/SM) + grid barrier + fused reduce.
// ============================================================================
#define GBK  32
#define GSPL 37
#define NKT  392
#define LDH  40
#define GSTAGE (128 * LDH)
#define GSMEM_BYTES (3 * GSTAGE * 2 * 2)

__global__ __launch_bounds__(256) void gemm_reduce_kernel(float* __restrict__ out) {
    extern __shared__ __align__(16) __half ghs[];
    __half* gA = ghs;
    __half* gB = ghs + 3 * GSTAGE;
    uint32_t sA = smem_u32(gA);
    uint32_t sB = smem_u32(gB);

    int tid = threadIdx.x;
    int wid = tid >> 5, lane = tid & 31;
    int m0 = blockIdx.x * 128;
    int o0 = blockIdx.y * 128;
    int t0 = (blockIdx.z * NKT) / GSPL;
    int t1 = ((blockIdx.z + 1) * NKT) / GSPL;
    int nt = t1 - t0;
    int k0 = t0 * GBK;

    int wm = (wid >> 1) * 32;
    int wn = (wid & 1) * 64;
    int gID = lane >> 2;
    int tg  = lane & 3;

    uint32_t aoff = (uint32_t)((wm + ((lane >> 3) & 1) * 8 + (lane & 7)) * LDH
                               + (lane >> 4) * 8) * 2;
    uint32_t boff = (uint32_t)((wn + (lane >> 4) * 8 + (lane & 7)) * LDH
                               + ((lane >> 3) & 1) * 8) * 2;

    float acc[2][8][4];
    #pragma unroll
    for (int mi = 0; mi < 2; mi++)
        #pragma unroll
        for (int ni = 0; ni < 8; ni++)
            #pragma unroll
            for (int r = 0; r < 4; r++) acc[mi][ni][r] = 0.0f;

    auto issue = [&](int t, int st) {
        int kt = k0 + t * GBK;
        uint32_t dA = sA + (uint32_t)(st * GSTAGE) * 2;
        uint32_t dB = sB + (uint32_t)(st * GSTAGE) * 2;
        #pragma unroll
        for (int j = 0; j < 2; j++) {
            int i   = tid + j * 256;
            int row = i >> 2;
            int c8  = i & 3;
            uint32_t so = (uint32_t)(row * LDH + c8 * 8) * 2;
            cpasync16(dA + so, g_roi + (size_t)(m0 + row) * KDIM + kt + c8 * 8);
            cpasync16(dB + so, g_bh  + (size_t)(o0 + row) * KDIM + kt + c8 * 8);
        }
        CP_COMMIT();
    };

    issue(0, 0);
    issue(1, 1);

    for (int t = 0; t < nt; t++) {
        if (t < nt - 1) { CP_WAIT(1); } else { CP_WAIT(0); }
        __syncthreads();
        if (t + 2 < nt) issue(t + 2, (t + 2) % 3);

        int st = t % 3;
        uint32_t stA = sA + (uint32_t)(st * GSTAGE) * 2;
        uint32_t stB = sB + (uint32_t)(st * GSTAGE) * 2;

        #pragma unroll
        for (int ks = 0; ks < 2; ks++) {
            uint32_t kadd = (uint32_t)(ks * 16) * 2;
            uint32_t af[2][4];
            ldsm_x4(af[0], stA + aoff + kadd);
            ldsm_x4(af[1], stA + aoff + (uint32_t)(16 * LDH) * 2 + kadd);
            uint32_t bf[8][2];
            #pragma unroll
            for (int np = 0; np < 4; np++) {
                uint32_t bq[4];
                ldsm_x4(bq, stB + boff + (uint32_t)(np * 16 * LDH) * 2 + kadd);
                bf[2 * np][0]     = bq[0];
                bf[2 * np][1]     = bq[1];
                bf[2 * np + 1][0] = bq[2];
                bf[2 * np + 1][1] = bq[3];
            }
            #pragma unroll
            for (int mi = 0; mi < 2; mi++)
                #pragma unroll
                for (int ni = 0; ni < 8; ni++)
                    mma_f16(acc[mi][ni], af[mi], bf[ni]);
        }
    }

    float* pp = g_part + (size_t)blockIdx.z * 65536;
    #pragma unroll
    for (int mi = 0; mi < 2; mi++) {
        #pragma unroll
        for (int ni = 0; ni < 8; ni++) {
            int rbase = m0 + wm + mi * 16 + gID;
            int cbase = o0 + wn + ni * 8 + tg * 2;
            *(float2*)(pp + (size_t)rbase * CCH + cbase)       = make_float2(acc[mi][ni][0], acc[mi][ni][1]);
            *(float2*)(pp + (size_t)(rbase + 8) * CCH + cbase) = make_float2(acc[mi][ni][2], acc[mi][ni][3]);
        }
    }

    // ---- software grid barrier (148 CTAs, all resident at 1 CTA/SM) ----
    __threadfence();
    __syncthreads();
    if (tid == 0) {
        unsigned a = atomicAdd(&g_bar, 1u);          // epoch-monotone, replay-safe
        unsigned tgt = (a / 148u + 1u) * 148u;
        while (*(volatile unsigned*)&g_bar < tgt) { }
        __threadfence();
    }
    __syncthreads();

    // ---- fused reduce: one float4 per thread (16384 needed, 37888 available) ----
    int flat = blockIdx.x + (blockIdx.y << 1) + (blockIdx.z << 2);
    int idx = flat * 256 + tid;
    if (idx < 16384) {
        size_t i = (size_t)idx * 4;
        float4 a = *(float4*)(out + i);
        #pragma unroll 7
        for (int s = 0; s < GSPL; s++) {
            float4 p = *(const float4*)(g_part + (size_t)s * 65536 + i);
            a.x += p.x; a.y += p.y; a.z += p.z; a.w += p.w;
        }
        *(float4*)(out + i) = a;
    }
}

// ============================================================================
// Launcher: fork-join stream overlap (R13 structure, reduce fused into gemm).
// ============================================================================
extern "C" void kernel_launch(void* const* d_in, const int* in_sizes, int n_in,
                              void* d_out, int out_size) {
    const float* img    = (const float*)d_in[0];
    const float* boxes  = (const float*)d_in[1];
    const float* conv_w = (const float*)d_in[2];
    const float* conv_b = (const float*)d_in[3];
    const float* cxw    = (const float*)d_in[4];
    const float* cxb    = (const float*)d_in[5];
    const float* pw     = (const float*)d_in[6];
    const float* pb     = (const float*)d_in[7];
    float* out = (float*)d_out;

    static cudaStream_t s1 = nullptr, s2 = nullptr;
    static cudaEvent_t ev0 = nullptr, ev1 = nullptr, ev2 = nullptr;
    static bool init_done = false;
    if (!init_done) {
        cudaFuncSetAttribute(gemm_reduce_kernel,
                             cudaFuncAttributeMaxDynamicSharedMemorySize, GSMEM_BYTES);
        cudaStreamCreateWithFlags(&s1, cudaStreamNonBlocking);
        cudaStreamCreateWithFlags(&s2, cudaStreamNonBlocking);
        cudaEventCreateWithFlags(&ev0, cudaEventDisableTiming);
        cudaEventCreateWithFlags(&ev1, cudaEventDisableTiming);
        cudaEventCreateWithFlags(&ev2, cudaEventDisableTiming);
        init_done = true;
    }

    // fork
    cudaEventRecord(ev0, 0);
    cudaStreamWaitEvent(s1, ev0, 0);
    cudaStreamWaitEvent(s2, ev0, 0);

    // side branches
    convp_kernel<<<256, 128, 0, s1>>>(conv_w);
    cudaEventRecord(ev1, s1);
    pos_kernel<<<dim3(64, 4), 256, 0, s2>>>(boxes, cxw, cxb, pw, pb, conv_b, out);
    cudaEventRecord(ev2, s2);

    // main chain
    trans_kernel<<<dim3(64, 4, 4), 256>>>(img);
    roi_kernel<<<dim3(256, 4), 224>>>(boxes);

    cudaStreamWaitEvent(0, ev1, 0);          // gemm needs convp
    cudaStreamWaitEvent(0, ev2, 0);          // fused reduce needs pos
    dim3 ggrid(2, 2, GSPL);
    gemm_reduce_kernel<<<ggrid, 256, GSMEM_BYTES>>>(out);
}